// round 11
// baseline (speedup 1.0000x reference)
#include <cuda_runtime.h>
#include <cuda_bf16.h>
#include <math.h>

// Problem constants
#define TT     1024
#define DD     4
#define PP     8
#define DPW    32                    // D*P
#define SS     256                   // N * N_SAMPLE
#define LT     8                     // timesteps per chunk
#define NCHUNK 128                   // chunks along T (128*8 = 1024)
#define QTR    4                     // blocks per sample in P1/P3
#define TBL    (TT*DPW)              // 32768 table elements
#define SZ     ((size_t)SS*TT*DPW)   // 8388608 elements per output tensor
#define HLOG2PI 0.91893853320467274178f

// Scratch (static __device__ arrays — allocation-free)
__device__ float  g_mean[TBL];
__device__ float  g_sw[TBL];
__device__ float  g_amul[TT*DD];          // sigmoid(a_raw[t-1,d]), amul[0,*]=0
__device__ float4 g_B[SS*NCHUNK*8];       // per-chunk local end values, 4 MB
__device__ float4 g_C[SS*NCHUNK*8];       // exclusive carries, 4 MB

// ---------------------------------------------------------------------------
// K0: precompute per-(t,dp) tables. Fast-math; tiny.
// ---------------------------------------------------------------------------
__global__ void arma_precompute(const float* __restrict__ m,
                                const float* __restrict__ s_raw,
                                const float* __restrict__ a_raw,
                                const int*   __restrict__ dim_idx)
{
    int idx = blockIdx.x * blockDim.x + threadIdx.x;
    if (idx >= TBL) return;
    int t  = idx >> 5;
    int dp = idx & 31;
    int dd = dp >> 3;
    int p  = dp & 7;
    int src = dim_idx[dd];

    float am = 0.0f;
    if (t > 0) {
        float x = a_raw[(t - 1) * DD + src];
        am = 1.0f / (1.0f + __expf(-x));
    }

    float sv = s_raw[t * DPW + src * PP + p];
    float sw = (sv > 20.0f) ? sv : __logf(1.0f + __expf(sv));   // softplus
    float mn = (1.0f - am) * m[t * DPW + src * PP + p];

    g_mean[idx] = mn;
    g_sw[idx]   = sw;
    if (p == 0) g_amul[t * DD + dd] = am;
}

// ---------------------------------------------------------------------------
// P1: stream noise once (float4, DEFAULT policy so L2 retains it for P3),
// write lp (__stcs, never re-read), emit per-chunk summaries b.
// Grid: 1024 blocks (s, quarter) x 256 threads (32 chunks x 8 quads).
// 8-warp blocks, ~32 regs -> 4 blocks/SM -> full occupancy in steady state.
// ---------------------------------------------------------------------------
__global__ void __launch_bounds__(256)
arma_pass1(const float4* __restrict__ noise4,
           float4* __restrict__ lp4,
           int write_lp)
{
    const int s     = blockIdx.x >> 2;
    const int qt    = blockIdx.x & 3;
    const int q     = threadIdx.x & 7;                  // dp quad: dp = 4q..4q+3
    const int chunk = (qt << 5) + (threadIdx.x >> 3);   // 0..127
    const int dd    = q >> 1;
    const int t0    = chunk << 3;

    const float4* tbl_sw = (const float4*)g_sw;
    const float4* tbl_mn = (const float4*)g_mean;

    const size_t base = ((size_t)((s << 10) + t0) << 3) + q;   // float4 index

    float4 b = make_float4(0.f, 0.f, 0.f, 0.f);

#pragma unroll
    for (int i = 0; i < LT; i++) {
        const int t  = t0 + i;
        const int ti = (t << 3) + q;
        const float4 n = noise4[base + (size_t)i * 8];         // keep in L2
        const float4 sw = tbl_sw[ti];
        const float4 mn = tbl_mn[ti];
        if (write_lp) {
            float4 lp;
            lp.x = fmaf(-0.5f * n.x, n.x, -__logf(sw.x) - HLOG2PI);
            lp.y = fmaf(-0.5f * n.y, n.y, -__logf(sw.y) - HLOG2PI);
            lp.z = fmaf(-0.5f * n.z, n.z, -__logf(sw.z) - HLOG2PI);
            lp.w = fmaf(-0.5f * n.w, n.w, -__logf(sw.w) - HLOG2PI);
            __stcs(&lp4[base + (size_t)i * 8], lp);
        }
        const float am = g_amul[(t << 2) + dd];
        b.x = fmaf(am, b.x, fmaf(sw.x, n.x, mn.x));
        b.y = fmaf(am, b.y, fmaf(sw.y, n.y, mn.y));
        b.z = fmaf(am, b.z, fmaf(sw.z, n.z, mn.z));
        b.w = fmaf(am, b.w, fmaf(sw.w, n.w, mn.w));
    }
    g_B[(((size_t)s << 7) + chunk) * 8 + q] = b;
}

// ---------------------------------------------------------------------------
// P2: per-sample scan entirely in shared memory. One 256-thread block per
// sample: load amul (16KB) + summaries B (16KB) into smem, per-chunk products
// in-block, warp0 runs the 128-step fma carry chain (~512 cyc), coalesced
// carry writeback.
// ---------------------------------------------------------------------------
__global__ void __launch_bounds__(256)
arma_scan()
{
    const int s   = blockIdx.x;
    const int tid = threadIdx.x;

    __shared__ float s_am[TT * DD];       // 16 KB
    __shared__ float sA[NCHUNK][DD];      // 2 KB
    __shared__ float sB[NCHUNK][DPW];     // 16 KB

    // Load amul: 4096 floats = 1024 float4, 4 per thread
#pragma unroll
    for (int k = 0; k < 4; k++)
        ((float4*)s_am)[tid + 256 * k] = ((const float4*)g_amul)[tid + 256 * k];

    // Load B: 128*32 floats = 1024 float4, 4 per thread
    const float4* Bs = g_B + ((size_t)s << 7) * 8;
#pragma unroll
    for (int k = 0; k < 4; k++)
        ((float4*)sB)[tid + 256 * k] = Bs[tid + 256 * k];
    __syncthreads();

    // Per-chunk amul products: 512 (chunk, d) pairs, 2 per thread
#pragma unroll
    for (int k = 0; k < 2; k++) {
        const int idx = tid + 256 * k;
        const int c  = idx >> 2;
        const int d2 = idx & 3;
        float a = 1.0f;
#pragma unroll
        for (int i = 0; i < LT; i++)
            a *= s_am[(((c << 3) + i) << 2) + d2];
        sA[c][d2] = a;
    }
    __syncthreads();

    // Warp0: serial affine scan over 128 chunks, one dp chain per lane.
    if (tid < 32) {
        const int dp = tid;
        const int d2 = dp >> 3;
        float* Cf = (float*)g_C + ((size_t)s << 7) * 32;
        float carry = 0.0f;
#pragma unroll
        for (int c = 0; c < NCHUNK; c++) {
            Cf[c * 32 + dp] = carry;                       // coalesced 128B
            carry = fmaf(sA[c][d2], carry, sB[c][dp]);
        }
    }
}

// ---------------------------------------------------------------------------
// P3: replay recursion with correct carries; noise re-read is an L2 hit.
// Same geometry as P1.
// ---------------------------------------------------------------------------
__global__ void __launch_bounds__(256)
arma_pass2(const float4* __restrict__ noise4,
           float4* __restrict__ param4)
{
    const int s     = blockIdx.x >> 2;
    const int qt    = blockIdx.x & 3;
    const int q     = threadIdx.x & 7;
    const int chunk = (qt << 5) + (threadIdx.x >> 3);
    const int dd    = q >> 1;
    const int t0    = chunk << 3;

    const float4* tbl_sw = (const float4*)g_sw;
    const float4* tbl_mn = (const float4*)g_mean;

    const size_t base = ((size_t)((s << 10) + t0) << 3) + q;

    float4 pv = g_C[(((size_t)s << 7) + chunk) * 8 + q];

#pragma unroll
    for (int i = 0; i < LT; i++) {
        const int t  = t0 + i;
        const int ti = (t << 3) + q;
        const float4 n  = noise4[base + (size_t)i * 8];   // L2 hit (read in P1)
        const float4 sw = tbl_sw[ti];
        const float4 mn = tbl_mn[ti];
        const float am  = g_amul[(t << 2) + dd];
        pv.x = fmaf(am, pv.x, fmaf(sw.x, n.x, mn.x));
        pv.y = fmaf(am, pv.y, fmaf(sw.y, n.y, mn.y));
        pv.z = fmaf(am, pv.z, fmaf(sw.z, n.z, mn.z));
        pv.w = fmaf(am, pv.w, fmaf(sw.w, n.w, mn.w));
        __stcs(&param4[base + (size_t)i * 8], pv);
    }
}

// ---------------------------------------------------------------------------
// Launch.  Inputs: 0:y 1:age 2:m 3:s_raw 4:a_raw 5:noise 6:cond_sample
//                  7:dim_idx 8:compute_log_prob
// Output: param (S,T,D,P) then log_prob (S,T,D,P), float32.
// ---------------------------------------------------------------------------
extern "C" void kernel_launch(void* const* d_in, const int* in_sizes, int n_in,
                              void* d_out, int out_size)
{
    const float* m      = (const float*)d_in[2];
    const float* s_raw  = (const float*)d_in[3];
    const float* a_raw  = (const float*)d_in[4];
    const float* noise  = (const float*)d_in[5];
    const int*   dimidx = (const int*)  d_in[7];

    float* out_param = (float*)d_out;
    int write_lp = (out_size >= (int)(2 * SZ)) ? 1 : 0;
    float* out_lp = out_param + SZ;

    const float4* noise4 = (const float4*)noise;
    float4* param4 = (float4*)out_param;
    float4* lp4    = (float4*)(write_lp ? out_lp : out_param);

    arma_precompute<<<256, 128>>>(m, s_raw, a_raw, dimidx);
    arma_pass1<<<SS * QTR, 256>>>(noise4, lp4, write_lp);
    arma_scan<<<SS, 256>>>();
    arma_pass2<<<SS * QTR, 256>>>(noise4, param4);
}

// round 12
// speedup vs baseline: 1.0778x; 1.0778x over previous
#include <cuda_runtime.h>
#include <cuda_bf16.h>
#include <math.h>

// Problem constants
#define TT     1024
#define DD     4
#define PP     8
#define DPW    32                    // D*P
#define SS     256                   // N * N_SAMPLE
#define LT     16                    // timesteps per chunk (deep MLP for DRAM pass)
#define NCHUNK 64                    // chunks along T (64*16 = 1024)
#define QTR    4                     // blocks per sample in P1/P3
#define TBL    (TT*DPW)              // 32768 table elements
#define SZ     ((size_t)SS*TT*DPW)   // 8388608 elements per output tensor
#define HLOG2PI 0.91893853320467274178f

// Scratch (static __device__ arrays — allocation-free)
__device__ float  g_mean[TBL];
__device__ float  g_sw[TBL];
__device__ float  g_amul[TT*DD];          // sigmoid(a_raw[t-1,d]), amul[0,*]=0
__device__ float4 g_B[SS*NCHUNK*8];       // per-chunk local end values, 2 MB
__device__ float4 g_C[SS*NCHUNK*8];       // exclusive carries, 2 MB

// ---------------------------------------------------------------------------
// K0: precompute per-(t,dp) tables. Fast-math; tiny.
// ---------------------------------------------------------------------------
__global__ void arma_precompute(const float* __restrict__ m,
                                const float* __restrict__ s_raw,
                                const float* __restrict__ a_raw,
                                const int*   __restrict__ dim_idx)
{
    int idx = blockIdx.x * blockDim.x + threadIdx.x;
    if (idx >= TBL) return;
    int t  = idx >> 5;
    int dp = idx & 31;
    int dd = dp >> 3;
    int p  = dp & 7;
    int src = dim_idx[dd];

    float am = 0.0f;
    if (t > 0) {
        float x = a_raw[(t - 1) * DD + src];
        am = 1.0f / (1.0f + __expf(-x));
    }

    float sv = s_raw[t * DPW + src * PP + p];
    float sw = (sv > 20.0f) ? sv : __logf(1.0f + __expf(sv));   // softplus
    float mn = (1.0f - am) * m[t * DPW + src * PP + p];

    g_mean[idx] = mn;
    g_sw[idx]   = sw;
    if (p == 0) g_amul[t * DD + dd] = am;
}

// ---------------------------------------------------------------------------
// P1: stream noise once (float4, DEFAULT policy so L2 retains it for P3),
// write lp (__stcs, never re-read), emit per-chunk summaries b.
// Grid: 1024 blocks (s, quarter) x 128 threads (16 chunks x 8 quads, LT=16).
// Small blocks give ~7 blocks/SM (occupancy) while LT=16 keeps 16 independent
// float4 loads in flight per thread (DRAM latency hiding).
// ---------------------------------------------------------------------------
__global__ void __launch_bounds__(128)
arma_pass1(const float4* __restrict__ noise4,
           float4* __restrict__ lp4,
           int write_lp)
{
    const int s     = blockIdx.x >> 2;
    const int qt    = blockIdx.x & 3;
    const int q     = threadIdx.x & 7;                  // dp quad: dp = 4q..4q+3
    const int chunk = (qt << 4) + (threadIdx.x >> 3);   // 0..63
    const int dd    = q >> 1;
    const int t0    = chunk << 4;

    const float4* tbl_sw = (const float4*)g_sw;
    const float4* tbl_mn = (const float4*)g_mean;

    const size_t base = ((size_t)((s << 10) + t0) << 3) + q;   // float4 index

    float4 b = make_float4(0.f, 0.f, 0.f, 0.f);

#pragma unroll
    for (int i = 0; i < LT; i++) {
        const int t  = t0 + i;
        const int ti = (t << 3) + q;
        const float4 n = noise4[base + (size_t)i * 8];         // keep in L2
        const float4 sw = tbl_sw[ti];
        const float4 mn = tbl_mn[ti];
        if (write_lp) {
            float4 lp;
            lp.x = fmaf(-0.5f * n.x, n.x, -__logf(sw.x) - HLOG2PI);
            lp.y = fmaf(-0.5f * n.y, n.y, -__logf(sw.y) - HLOG2PI);
            lp.z = fmaf(-0.5f * n.z, n.z, -__logf(sw.z) - HLOG2PI);
            lp.w = fmaf(-0.5f * n.w, n.w, -__logf(sw.w) - HLOG2PI);
            __stcs(&lp4[base + (size_t)i * 8], lp);
        }
        const float am = g_amul[(t << 2) + dd];
        b.x = fmaf(am, b.x, fmaf(sw.x, n.x, mn.x));
        b.y = fmaf(am, b.y, fmaf(sw.y, n.y, mn.y));
        b.z = fmaf(am, b.z, fmaf(sw.z, n.z, mn.z));
        b.w = fmaf(am, b.w, fmaf(sw.w, n.w, mn.w));
    }
    g_B[(((size_t)s << 6) + chunk) * 8 + q] = b;
}

// ---------------------------------------------------------------------------
// P2: per-sample scan entirely in shared memory (identical to R10's winner).
// One 256-thread block per sample: load amul (16KB) + summaries B (8KB) into
// smem, per-chunk products in-block, warp0 runs the 64-step fma carry chain,
// coalesced carry writeback.
// ---------------------------------------------------------------------------
__global__ void __launch_bounds__(256)
arma_scan()
{
    const int s   = blockIdx.x;
    const int tid = threadIdx.x;

    __shared__ float s_am[TT * DD];       // 16 KB
    __shared__ float sA[NCHUNK][DD];      // 1 KB
    __shared__ float sB[NCHUNK][DPW];     // 8 KB

    // Load amul: 4096 floats = 1024 float4, 4 per thread
#pragma unroll
    for (int k = 0; k < 4; k++)
        ((float4*)s_am)[tid + 256 * k] = ((const float4*)g_amul)[tid + 256 * k];

    // Load B: 512 float4, 2 per thread
    const float4* Bs = g_B + ((size_t)s << 6) * 8;
    ((float4*)sB)[tid]       = Bs[tid];
    ((float4*)sB)[tid + 256] = Bs[tid + 256];
    __syncthreads();

    // Per-chunk amul products: one (chunk, d) per thread
    {
        const int c  = tid >> 2;
        const int d2 = tid & 3;
        float a = 1.0f;
#pragma unroll
        for (int i = 0; i < LT; i++)
            a *= s_am[(((c << 4) + i) << 2) + d2];
        sA[c][d2] = a;
    }
    __syncthreads();

    // Warp0: serial affine scan over 64 chunks, one dp chain per lane.
    if (tid < 32) {
        const int dp = tid;
        const int d2 = dp >> 3;
        float* Cf = (float*)g_C + ((size_t)s << 6) * 32;
        float carry = 0.0f;
#pragma unroll
        for (int c = 0; c < NCHUNK; c++) {
            Cf[c * 32 + dp] = carry;                       // coalesced 128B
            carry = fmaf(sA[c][d2], carry, sB[c][dp]);
        }
    }
}

// ---------------------------------------------------------------------------
// P3: replay recursion with correct carries; noise re-read is an L2 hit.
// Same geometry as P1 (1024 blocks x 128 threads, LT=16).
// ---------------------------------------------------------------------------
__global__ void __launch_bounds__(128)
arma_pass2(const float4* __restrict__ noise4,
           float4* __restrict__ param4)
{
    const int s     = blockIdx.x >> 2;
    const int qt    = blockIdx.x & 3;
    const int q     = threadIdx.x & 7;
    const int chunk = (qt << 4) + (threadIdx.x >> 3);
    const int dd    = q >> 1;
    const int t0    = chunk << 4;

    const float4* tbl_sw = (const float4*)g_sw;
    const float4* tbl_mn = (const float4*)g_mean;

    const size_t base = ((size_t)((s << 10) + t0) << 3) + q;

    float4 pv = g_C[(((size_t)s << 6) + chunk) * 8 + q];

#pragma unroll
    for (int i = 0; i < LT; i++) {
        const int t  = t0 + i;
        const int ti = (t << 3) + q;
        const float4 n  = noise4[base + (size_t)i * 8];   // L2 hit (read in P1)
        const float4 sw = tbl_sw[ti];
        const float4 mn = tbl_mn[ti];
        const float am  = g_amul[(t << 2) + dd];
        pv.x = fmaf(am, pv.x, fmaf(sw.x, n.x, mn.x));
        pv.y = fmaf(am, pv.y, fmaf(sw.y, n.y, mn.y));
        pv.z = fmaf(am, pv.z, fmaf(sw.z, n.z, mn.z));
        pv.w = fmaf(am, pv.w, fmaf(sw.w, n.w, mn.w));
        __stcs(&param4[base + (size_t)i * 8], pv);
    }
}

// ---------------------------------------------------------------------------
// Launch.  Inputs: 0:y 1:age 2:m 3:s_raw 4:a_raw 5:noise 6:cond_sample
//                  7:dim_idx 8:compute_log_prob
// Output: param (S,T,D,P) then log_prob (S,T,D,P), float32.
// ---------------------------------------------------------------------------
extern "C" void kernel_launch(void* const* d_in, const int* in_sizes, int n_in,
                              void* d_out, int out_size)
{
    const float* m      = (const float*)d_in[2];
    const float* s_raw  = (const float*)d_in[3];
    const float* a_raw  = (const float*)d_in[4];
    const float* noise  = (const float*)d_in[5];
    const int*   dimidx = (const int*)  d_in[7];

    float* out_param = (float*)d_out;
    int write_lp = (out_size >= (int)(2 * SZ)) ? 1 : 0;
    float* out_lp = out_param + SZ;

    const float4* noise4 = (const float4*)noise;
    float4* param4 = (float4*)out_param;
    float4* lp4    = (float4*)(write_lp ? out_lp : out_param);

    arma_precompute<<<256, 128>>>(m, s_raw, a_raw, dimidx);
    arma_pass1<<<SS * QTR, 128>>>(noise4, lp4, write_lp);
    arma_scan<<<SS, 256>>>();
    arma_pass2<<<SS * QTR, 128>>>(noise4, param4);
}